// round 4
// baseline (speedup 1.0000x reference)
#include <cuda_runtime.h>
#include <math.h>

#define HID   64
#define NPT   128
#define LBF   (-5.0f)
#define BPB   8      // batches per block

__device__ __forceinline__ unsigned f2tf32(float x) {
    unsigned r;
    asm("cvt.rna.tf32.f32 %0, %1;\n" : "=r"(r) : "f"(x));
    return r;
}

__device__ __forceinline__ void mma_tf32(float c[4],
                                         unsigned a0, unsigned a1, unsigned a2, unsigned a3,
                                         unsigned b0, unsigned b1) {
    asm volatile(
        "mma.sync.aligned.m16n8k8.row.col.f32.tf32.tf32.f32 "
        "{%0,%1,%2,%3}, {%4,%5,%6,%7}, {%8,%9}, {%0,%1,%2,%3};\n"
        : "+f"(c[0]), "+f"(c[1]), "+f"(c[2]), "+f"(c[3])
        : "r"(a0), "r"(a1), "r"(a2), "r"(a3), "r"(b0), "r"(b1));
}

__device__ __forceinline__ float lrelu(float h) { return fmaxf(h, 0.01f * h); }

// Transposed-GEMM kernel: A = W2 (j-rows, persistent regs), B = H1 (built on the fly)
__global__ __launch_bounds__(256)
void mono_mlp_tc3_kernel(const float* __restrict__ z,  const float* __restrict__ u,
                         const float* __restrict__ w01, const float* __restrict__ b01,
                         const float* __restrict__ w02, const float* __restrict__ b02,
                         const float* __restrict__ w03, const float* __restrict__ b03,
                         const float* __restrict__ w11, const float* __restrict__ b11,
                         const float* __restrict__ w12, const float* __restrict__ b12,
                         const float* __restrict__ w13, const float* __restrict__ b13,
                         const float* __restrict__ bias, float* __restrict__ out, int B)
{
    // A fragments (W2 as tf32) in mma order: afrag[((d*4+q)*8+kt)*32 + lane]
    //   .x = W2[j0][k0]  .y = W2[j1][k0]  .z = W2[j0][k1]  .w = W2[j1][k1]
    //   j0 = 16q+gid, j1 = j0+8, k0 = 8kt+tig, k1 = k0+4
    __shared__ uint4  afrag[2 * 4 * 8 * 32];   // 32 KB
    __shared__ float2 w1b1[2][HID];            // (w1[k], b1[k])
    __shared__ float2 w3b2[2][HID];            // (w3[j], b2[j])
    __shared__ float  b3s[2];
    __shared__ float  xs[NPT];                 // layer-0 inputs for current (b,d)
    __shared__ float  sred[4][NPT];            // per-point partials, 4 col-quads
    __shared__ float  hzacc[BPB];

    const int tid = threadIdx.x;

    // ---- Prepack weights (once per block, amortized over 16 (b,d)-tiles) ----
    for (int e = tid; e < 2 * 4 * 8 * 32; e += 256) {
        const int lane = e & 31;
        const int kt   = (e >> 5) & 7;
        const int q    = (e >> 8) & 3;
        const int d    = (e >> 10) & 1;
        const int gid  = lane >> 2, tig = lane & 3;
        const int j0 = 16 * q + gid, j1 = j0 + 8;
        const int k0 = 8 * kt + tig, k1 = k0 + 4;
        const float* w2 = d ? w12 : w02;
        afrag[e] = make_uint4(f2tf32(w2[j0 * 64 + k0]), f2tf32(w2[j1 * 64 + k0]),
                              f2tf32(w2[j0 * 64 + k1]), f2tf32(w2[j1 * 64 + k1]));
    }
    if (tid < HID) {
        w1b1[0][tid] = make_float2(w01[tid], b01[tid]);
        w1b1[1][tid] = make_float2(w11[tid], b11[tid]);
        w3b2[0][tid] = make_float2(w03[tid], b02[tid]);
        w3b2[1][tid] = make_float2(w13[tid], b12[tid]);
    }
    if (tid == 0) { b3s[0] = b03[0]; b3s[1] = b13[0]; }
    if (tid < BPB) hzacc[tid] = bias[0];
    __syncthreads();

    const int warp  = tid >> 5;
    const int lane  = tid & 31;
    const int gid   = lane >> 2;
    const int tig   = lane & 3;
    const int q     = warp & 3;        // col-quad: j in [16q, 16q+16)
    const int phalf = warp >> 2;       // points [64*phalf, +64)
    const int pbase = 64 * phalf;
    const int j0    = 16 * q + gid;    // this lane's two j rows
    // epilogue weights for j0, j0+8 (constant per d)

    #pragma unroll 1
    for (int d = 0; d < 2; d++) {
        // A fragments (W2) for this warp: 8 kt x 4 regs, persistent
        uint4 afr[8];
        {
            const uint4* ap = &afrag[((d * 4 + q) * 8) * 32 + lane];
            #pragma unroll
            for (int kt = 0; kt < 8; kt++) afr[kt] = ap[kt * 32];
        }
        const float2 e0 = w3b2[d][j0];
        const float2 e1 = w3b2[d][j0 + 8];
        const float  b3v = b3s[d];

        #pragma unroll 1
        for (int bi = 0; bi < BPB; bi++) {
            const int b = blockIdx.x * BPB + bi;

            const float zc  = fmaxf(z[b * 2 + d], LBF);
            const float dsz = (zc - LBF) * (1.0f / (float)(NPT - 1));
            const int   ub  = (b * 2 + d) * (NPT - 1);

            // ---- stage 1: layer-0 inputs for all 128 points ----
            if (tid < NPT) {
                const float uv = (tid < NPT - 1) ? u[ub + tid] : 0.0f;
                xs[tid] = fmaf(dsz, (float)tid + uv, LBF);
            }
            __syncthreads();   // (A)

            // ---- stage 2: GEMM C'[j][p], 2 rounds of 4 concurrent point-tiles ----
            #pragma unroll 1
            for (int rnd = 0; rnd < 2; rnd++) {
                const int prow = pbase + 32 * rnd;

                float acc[4][4];
                #pragma unroll
                for (int t = 0; t < 4; t++)
                    #pragma unroll
                    for (int c = 0; c < 4; c++) acc[t][c] = 0.0f;

                // x for this lane's point in each of the 4 tiles (n = gid)
                float x[4];
                #pragma unroll
                for (int t = 0; t < 4; t++) x[t] = xs[prow + 8 * t + gid];

                #pragma unroll
                for (int kt = 0; kt < 8; kt++) {
                    const float2 wa = w1b1[d][8 * kt + tig];       // k0
                    const float2 wb = w1b1[d][8 * kt + tig + 4];   // k1
                    const uint4  a  = afr[kt];
                    #pragma unroll
                    for (int t = 0; t < 4; t++) {
                        const unsigned b0 = __float_as_uint(lrelu(fmaf(x[t], wa.x, wa.y)));
                        const unsigned b1 = __float_as_uint(lrelu(fmaf(x[t], wb.x, wb.y)));
                        mma_tf32(acc[t], a.x, a.y, a.z, a.w, b0, b1);
                    }
                }

                // ---- stage 3: epilogue per point-tile ----
                #pragma unroll
                for (int t = 0; t < 4; t++) {
                    // points 2tig, 2tig+1 of tile; rows j0, j0+8
                    float v0 = fmaf(lrelu(acc[t][0] + e0.y), e0.x,
                                    lrelu(acc[t][2] + e1.y) * e1.x);
                    float v1 = fmaf(lrelu(acc[t][1] + e0.y), e0.x,
                                    lrelu(acc[t][3] + e1.y) * e1.x);
                    // sum over the 8 gid groups (16 j's per col-quad)
                    v0 += __shfl_xor_sync(0xffffffffu, v0, 4);
                    v0 += __shfl_xor_sync(0xffffffffu, v0, 8);
                    v0 += __shfl_xor_sync(0xffffffffu, v0, 16);
                    v1 += __shfl_xor_sync(0xffffffffu, v1, 4);
                    v1 += __shfl_xor_sync(0xffffffffu, v1, 8);
                    v1 += __shfl_xor_sync(0xffffffffu, v1, 16);
                    if (gid == 0) {
                        const int p = prow + 8 * t + 2 * tig;
                        sred[q][p]     = v0;
                        sred[q][p + 1] = v1;
                    }
                }
            }
            __syncthreads();   // (B)

            // ---- stage 4: combine col-quads, ELU, reduce 128 points (warp 0) ----
            if (warp == 0) {
                float tsum = 0.0f;
                #pragma unroll
                for (int i = 0; i < 4; i++) {
                    const int p = lane + 32 * i;
                    const float v = sred[0][p] + sred[1][p] + sred[2][p] + sred[3][p] + b3v;
                    tsum += ((v > 0.f) ? v : expm1f(v)) + 1.0f;
                }
                tsum += __shfl_xor_sync(0xffffffffu, tsum, 16);
                tsum += __shfl_xor_sync(0xffffffffu, tsum, 8);
                tsum += __shfl_xor_sync(0xffffffffu, tsum, 4);
                tsum += __shfl_xor_sync(0xffffffffu, tsum, 2);
                tsum += __shfl_xor_sync(0xffffffffu, tsum, 1);
                if (lane == 0) hzacc[bi] = fmaf(tsum, dsz, hzacc[bi]);
            }
            // next iteration's sync (A) orders stage-4 reads before sred rewrite
        }
    }

    __syncthreads();
    if (tid < BPB) {
        const int b = blockIdx.x * BPB + tid;
        if (b < B) out[b] = hzacc[tid];
    }
}

extern "C" void kernel_launch(void* const* d_in, const int* in_sizes, int n_in,
                              void* d_out, int out_size)
{
    const float* z   = (const float*)d_in[0];
    const float* u   = (const float*)d_in[1];
    const float* w01 = (const float*)d_in[2];
    const float* b01 = (const float*)d_in[3];
    const float* w02 = (const float*)d_in[4];
    const float* b02 = (const float*)d_in[5];
    const float* w03 = (const float*)d_in[6];
    const float* b03 = (const float*)d_in[7];
    const float* w11 = (const float*)d_in[8];
    const float* b11 = (const float*)d_in[9];
    const float* w12 = (const float*)d_in[10];
    const float* b12 = (const float*)d_in[11];
    const float* w13 = (const float*)d_in[12];
    const float* b13 = (const float*)d_in[13];
    const float* bias= (const float*)d_in[14];
    float* out = (float*)d_out;

    const int B = in_sizes[0] / 2;
    const int grid = (B + BPB - 1) / BPB;
    mono_mlp_tc3_kernel<<<grid, 256>>>(
        z, u, w01, b01, w02, b02, w03, b03,
        w11, b11, w12, b12, w13, b13, bias, out, B);
}

// round 5
// speedup vs baseline: 1.2467x; 1.2467x over previous
#include <cuda_runtime.h>
#include <math.h>

#define HID   64
#define NPT   128
#define LBF   (-5.0f)
#define BPB   8      // batches per block

__device__ __forceinline__ unsigned f2tf32(float x) {
    unsigned r;
    asm("cvt.rna.tf32.f32 %0, %1;\n" : "=r"(r) : "f"(x));
    return r;
}

__device__ __forceinline__ void mma_tf32(float c[4],
                                         unsigned a0, unsigned a1, unsigned a2, unsigned a3,
                                         unsigned b0, unsigned b1) {
    asm volatile(
        "mma.sync.aligned.m16n8k8.row.col.f32.tf32.tf32.f32 "
        "{%0,%1,%2,%3}, {%4,%5,%6,%7}, {%8,%9}, {%0,%1,%2,%3};\n"
        : "+f"(c[0]), "+f"(c[1]), "+f"(c[2]), "+f"(c[3])
        : "r"(a0), "r"(a1), "r"(a2), "r"(a3), "r"(b0), "r"(b1));
}

__device__ __forceinline__ float lrelu(float h) { return fmaxf(h, 0.01f * h); }

__global__ __launch_bounds__(256)
void mono_mlp_tc4_kernel(const float* __restrict__ z,  const float* __restrict__ u,
                         const float* __restrict__ w01, const float* __restrict__ b01,
                         const float* __restrict__ w02, const float* __restrict__ b02,
                         const float* __restrict__ w03, const float* __restrict__ b03,
                         const float* __restrict__ w11, const float* __restrict__ b11,
                         const float* __restrict__ w12, const float* __restrict__ b12,
                         const float* __restrict__ w13, const float* __restrict__ b13,
                         const float* __restrict__ bias, float* __restrict__ out, int B)
{
    // B fragments (tf32, mma order): bfrag[d*2048 + kt*256 + nt*32 + lane]
    __shared__ uint2  bfrag[2 * 8 * 8 * 32];   // 32 KB
    __shared__ float2 w1b1[2][HID];            // (w1[k], b1[k])
    __shared__ float2 w3b2[2][HID];            // (w3[j], b2[j])
    __shared__ float  b3s[2];
    __shared__ float  sred[2][NPT];            // per-point partials, 2 n-halves
    __shared__ float  red4[4];

    const int tid = threadIdx.x;

    // ---- Prepack weights (once per block) ----
    for (int e = tid; e < 2 * 8 * 8 * 32; e += 256) {
        const int lane = e & 31;
        const int nt   = (e >> 5) & 7;
        const int kt   = (e >> 8) & 7;
        const int d    = (e >> 11) & 1;
        const int n    = 8 * nt + (lane >> 2);
        const int k    = 8 * kt + (lane & 3);
        const float* w2 = d ? w12 : w02;
        bfrag[e] = make_uint2(f2tf32(w2[n * 64 + k]), f2tf32(w2[n * 64 + k + 4]));
    }
    if (tid < HID) {
        w1b1[0][tid] = make_float2(w01[tid], b01[tid]);
        w1b1[1][tid] = make_float2(w11[tid], b11[tid]);
        w3b2[0][tid] = make_float2(w03[tid], b02[tid]);
        w3b2[1][tid] = make_float2(w13[tid], b12[tid]);
    }
    if (tid == 0) { b3s[0] = b03[0]; b3s[1] = b13[0]; }
    __syncthreads();

    const int warp  = tid >> 5;
    const int lane  = tid & 31;
    const int gid   = lane >> 2;       // row within m16 group
    const int tig   = lane & 3;        // k / col selector
    const int phalf = warp >> 1;       // point group: [32*phalf, +32)
    const int nhalf = warp & 1;        // n half: [32*nhalf, +32)
    const int pbase = 32 * phalf;
    const int nbase = 32 * nhalf;

    const int p00 = pbase + gid;       // pt0 row0 (<= 103)
    const int p01 = p00 + 8;           // pt0 row1 (<= 111)
    const int p10 = p00 + 16;          // pt1 row0 (<= 119)
    const int p11 = p00 + 24;          // pt1 row1 (<= 127)
    const float biasv = bias[0];

    for (int bi = 0; bi < BPB; bi++) {
        const int b = blockIdx.x * BPB + bi;
        if (b >= B) break;
        float hz = biasv;   // meaningful on thread 0 only

        #pragma unroll 1
        for (int d = 0; d < 2; d++) {
            const float zc  = fmaxf(z[b * 2 + d], LBF);
            const float dsz = (zc - LBF) * (1.0f / (float)(NPT - 1));
            const int   ub  = (b * 2 + d) * (NPT - 1);

            // layer-0 inputs x at the 4 point rows
            const float u3  = (p11 < NPT - 1) ? u[ub + p11] : 0.0f;
            const float x00 = fmaf(dsz, (float)p00 + u[ub + p00], LBF);
            const float x01 = fmaf(dsz, (float)p01 + u[ub + p01], LBF);
            const float x10 = fmaf(dsz, (float)p10 + u[ub + p10], LBF);
            const float x11 = fmaf(dsz, (float)p11 + u3,          LBF);

            // ---- GEMM: 32 points x 32 n-cols per warp, K=64 ----
            float acc[2][4][4];
            #pragma unroll
            for (int pt = 0; pt < 2; pt++)
                #pragma unroll
                for (int nt = 0; nt < 4; nt++)
                    #pragma unroll
                    for (int c = 0; c < 4; c++) acc[pt][nt][c] = 0.0f;

            const uint2* bbase = &bfrag[d * 2048 + nhalf * 128 + lane];

            #pragma unroll
            for (int kt = 0; kt < 8; kt++) {
                // batched B-fragment loads (each feeds 2 mmas)
                const uint2* bp = bbase + kt * 256;
                const uint2 bf0 = bp[0];
                const uint2 bf1 = bp[32];
                const uint2 bf2 = bp[64];
                const uint2 bf3 = bp[96];

                // layer-1 weights via SMEM broadcast (4 distinct addrs / warp)
                const float2 wa = w1b1[d][8 * kt + tig];       // k0
                const float2 wb = w1b1[d][8 * kt + tig + 4];   // k1

                // A fragments (tf32 truncation happens in HW)
                const unsigned a00 = __float_as_uint(lrelu(fmaf(x00, wa.x, wa.y)));
                const unsigned a01 = __float_as_uint(lrelu(fmaf(x01, wa.x, wa.y)));
                const unsigned a02 = __float_as_uint(lrelu(fmaf(x00, wb.x, wb.y)));
                const unsigned a03 = __float_as_uint(lrelu(fmaf(x01, wb.x, wb.y)));
                const unsigned a10 = __float_as_uint(lrelu(fmaf(x10, wa.x, wa.y)));
                const unsigned a11 = __float_as_uint(lrelu(fmaf(x11, wa.x, wa.y)));
                const unsigned a12 = __float_as_uint(lrelu(fmaf(x10, wb.x, wb.y)));
                const unsigned a13 = __float_as_uint(lrelu(fmaf(x11, wb.x, wb.y)));

                mma_tf32(acc[0][0], a00, a01, a02, a03, bf0.x, bf0.y);
                mma_tf32(acc[0][1], a00, a01, a02, a03, bf1.x, bf1.y);
                mma_tf32(acc[0][2], a00, a01, a02, a03, bf2.x, bf2.y);
                mma_tf32(acc[0][3], a00, a01, a02, a03, bf3.x, bf3.y);
                mma_tf32(acc[1][0], a10, a11, a12, a13, bf0.x, bf0.y);
                mma_tf32(acc[1][1], a10, a11, a12, a13, bf1.x, bf1.y);
                mma_tf32(acc[1][2], a10, a11, a12, a13, bf2.x, bf2.y);
                mma_tf32(acc[1][3], a10, a11, a12, a13, bf3.x, bf3.y);
            }

            // ---- epilogue: bias + LeakyReLU, dot w3 over this warp's 32 n ----
            float s[2][2] = {{0.f, 0.f}, {0.f, 0.f}};   // [pt][row]
            #pragma unroll
            for (int nt = 0; nt < 4; nt++) {
                const int j0 = nbase + 8 * nt + 2 * tig;
                const float2 e0 = w3b2[d][j0];
                const float2 e1 = w3b2[d][j0 + 1];
                #pragma unroll
                for (int pt = 0; pt < 2; pt++) {
                    float h;
                    h = lrelu(acc[pt][nt][0] + e0.y); s[pt][0] = fmaf(h, e0.x, s[pt][0]);
                    h = lrelu(acc[pt][nt][1] + e1.y); s[pt][0] = fmaf(h, e1.x, s[pt][0]);
                    h = lrelu(acc[pt][nt][2] + e0.y); s[pt][1] = fmaf(h, e0.x, s[pt][1]);
                    h = lrelu(acc[pt][nt][3] + e1.y); s[pt][1] = fmaf(h, e1.x, s[pt][1]);
                }
            }
            // fold the tig quad -> per-point sums over the 32 n-cols
            #pragma unroll
            for (int pt = 0; pt < 2; pt++)
                #pragma unroll
                for (int r = 0; r < 2; r++) {
                    s[pt][r] += __shfl_xor_sync(0xffffffffu, s[pt][r], 1);
                    s[pt][r] += __shfl_xor_sync(0xffffffffu, s[pt][r], 2);
                }
            if (tig == 0) {
                sred[nhalf][p00] = s[0][0];
                sred[nhalf][p01] = s[0][1];
                sred[nhalf][p10] = s[1][0];
                sred[nhalf][p11] = s[1][1];
            }
            __syncthreads();

            // combine n-halves, ELU, block-reduce over 128 points
            if (tid < NPT) {
                const float v = sred[0][tid] + sred[1][tid] + b3s[d];
                float t = ((v > 0.f) ? v : expm1f(v)) + 1.0f;
                t += __shfl_xor_sync(0xffffffffu, t, 16);
                t += __shfl_xor_sync(0xffffffffu, t, 8);
                t += __shfl_xor_sync(0xffffffffu, t, 4);
                t += __shfl_xor_sync(0xffffffffu, t, 2);
                t += __shfl_xor_sync(0xffffffffu, t, 1);
                if ((tid & 31) == 0) red4[tid >> 5] = t;
            }
            __syncthreads();
            if (tid == 0)
                hz = fmaf(red4[0] + red4[1] + red4[2] + red4[3], dsz, hz);
        }
        if (tid == 0) out[b] = hz;
    }
}

extern "C" void kernel_launch(void* const* d_in, const int* in_sizes, int n_in,
                              void* d_out, int out_size)
{
    const float* z   = (const float*)d_in[0];
    const float* u   = (const float*)d_in[1];
    const float* w01 = (const float*)d_in[2];
    const float* b01 = (const float*)d_in[3];
    const float* w02 = (const float*)d_in[4];
    const float* b02 = (const float*)d_in[5];
    const float* w03 = (const float*)d_in[6];
    const float* b03 = (const float*)d_in[7];
    const float* w11 = (const float*)d_in[8];
    const float* b11 = (const float*)d_in[9];
    const float* w12 = (const float*)d_in[10];
    const float* b12 = (const float*)d_in[11];
    const float* w13 = (const float*)d_in[12];
    const float* b13 = (const float*)d_in[13];
    const float* bias= (const float*)d_in[14];
    float* out = (float*)d_out;

    const int B = in_sizes[0] / 2;
    const int grid = (B + BPB - 1) / BPB;
    mono_mlp_tc4_kernel<<<grid, 256>>>(
        z, u, w01, b01, w02, b02, w03, b03,
        w11, b11, w12, b12, w13, b13, bias, out, B);
}

// round 6
// speedup vs baseline: 1.8774x; 1.5059x over previous
#include <cuda_runtime.h>
#include <cuda_fp16.h>
#include <math.h>

#define HID   64
#define NPT   128
#define LBF   (-5.0f)
#define BPB   8      // batches per block

__device__ __forceinline__ unsigned pack_h2(float lo, float hi) {
    const __half2 h = __floats2half2_rn(lo, hi);
    return *reinterpret_cast<const unsigned*>(&h);
}

__device__ __forceinline__ void mma_f16(float c[4],
                                        unsigned a0, unsigned a1, unsigned a2, unsigned a3,
                                        unsigned b0, unsigned b1) {
    asm volatile(
        "mma.sync.aligned.m16n8k16.row.col.f32.f16.f16.f32 "
        "{%0,%1,%2,%3}, {%4,%5,%6,%7}, {%8,%9}, {%0,%1,%2,%3};\n"
        : "+f"(c[0]), "+f"(c[1]), "+f"(c[2]), "+f"(c[3])
        : "r"(a0), "r"(a1), "r"(a2), "r"(a3), "r"(b0), "r"(b1));
}

__device__ __forceinline__ float lrelu(float h) { return fmaxf(h, 0.01f * h); }

__global__ __launch_bounds__(256)
void mono_mlp_fp16_kernel(const float* __restrict__ z,  const float* __restrict__ u,
                          const float* __restrict__ w01, const float* __restrict__ b01,
                          const float* __restrict__ w02, const float* __restrict__ b02,
                          const float* __restrict__ w03, const float* __restrict__ b03,
                          const float* __restrict__ w11, const float* __restrict__ b11,
                          const float* __restrict__ w12, const float* __restrict__ b12,
                          const float* __restrict__ w13, const float* __restrict__ b13,
                          const float* __restrict__ bias, float* __restrict__ out, int B)
{
    // B fragments (fp16, m16n8k16 order): bfrag[d*1024 + kt*256 + nt*32 + lane]
    //   .x = half2(W2[n][k0], W2[n][k0+1]), .y = half2(W2[n][k0+8], W2[n][k0+9])
    //   n = 8nt + gid, k0 = 16kt + 2tig
    __shared__ uint2  bfrag[2 * 4 * 8 * 32];   // 16 KB
    __shared__ float4 w1b1p[2][HID / 2];       // (w1[2m], b1[2m], w1[2m+1], b1[2m+1])
    __shared__ float2 w3b2[2][HID];            // (w3[j], b2[j])
    __shared__ float  b3s[2];
    __shared__ float  sred[16][8];             // [warp-half pads][..] -> per-point partials
    __shared__ float  red4[4];

    const int tid = threadIdx.x;

    // ---- Prepack weights (once per block) ----
    for (int e = tid; e < 2 * 4 * 8 * 32; e += 256) {
        const int lane = e & 31;
        const int nt   = (e >> 5) & 7;
        const int kt   = (e >> 8) & 3;
        const int d    = (e >> 10) & 1;
        const int n    = 8 * nt + (lane >> 2);
        const int k0   = 16 * kt + 2 * (lane & 3);
        const float* w2 = d ? w12 : w02;
        bfrag[e] = make_uint2(pack_h2(w2[n * 64 + k0],     w2[n * 64 + k0 + 1]),
                              pack_h2(w2[n * 64 + k0 + 8], w2[n * 64 + k0 + 9]));
    }
    if (tid < HID / 2) {
        w1b1p[0][tid] = make_float4(w01[2 * tid], b01[2 * tid], w01[2 * tid + 1], b01[2 * tid + 1]);
        w1b1p[1][tid] = make_float4(w11[2 * tid], b11[2 * tid], w11[2 * tid + 1], b11[2 * tid + 1]);
    }
    if (tid < HID) {
        w3b2[0][tid] = make_float2(w03[tid], b02[tid]);
        w3b2[1][tid] = make_float2(w13[tid], b12[tid]);
    }
    if (tid == 0) { b3s[0] = b03[0]; b3s[1] = b13[0]; }
    __syncthreads();

    const int warp = tid >> 5;
    const int lane = tid & 31;
    const int gid  = lane >> 2;       // row within m16 group
    const int tig  = lane & 3;        // k / col selector
    const int p0   = 16 * warp + gid; // this thread's two point rows
    const int p1   = p0 + 8;
    const float biasv = bias[0];

    for (int bi = 0; bi < BPB; bi++) {
        const int b = blockIdx.x * BPB + bi;
        if (b >= B) break;
        float hz = biasv;   // meaningful on thread 0 only

        #pragma unroll 1
        for (int d = 0; d < 2; d++) {
            const float zc  = fmaxf(z[b * 2 + d], LBF);
            const float dsz = (zc - LBF) * (1.0f / (float)(NPT - 1));
            const int   ub  = (b * 2 + d) * (NPT - 1);

            // layer-0 inputs at the two point rows
            const float u0 = u[ub + p0];                           // p0 <= 119
            const float u1 = (p1 < NPT - 1) ? u[ub + p1] : 0.0f;   // p1 can be 127
            const float x0 = fmaf(dsz, (float)p0 + u0, LBF);
            const float x1 = fmaf(dsz, (float)p1 + u1, LBF);

            // ---- layer-2 GEMM: 16 points x 64 n-cols per warp, K=64, fp16 mma ----
            float acc[8][4];
            #pragma unroll
            for (int nt = 0; nt < 8; nt++)
                #pragma unroll
                for (int q = 0; q < 4; q++) acc[nt][q] = 0.0f;

            const uint2* bbase = &bfrag[d * 1024 + lane];

            #pragma unroll
            for (int kt = 0; kt < 4; kt++) {
                // layer-1 weights for k0,k0+1 and k0+8,k0+9 (broadcast LDS.128)
                const float4 wa = w1b1p[d][8 * kt + tig];       // k0, k0+1
                const float4 wb = w1b1p[d][8 * kt + tig + 4];   // k0+8, k0+9

                // A fragments: h1 at (p0/p1) x (k0,k0+1,k0+8,k0+9), rounded to fp16
                const unsigned a0 = pack_h2(lrelu(fmaf(x0, wa.x, wa.y)),
                                            lrelu(fmaf(x0, wa.z, wa.w)));
                const unsigned a1 = pack_h2(lrelu(fmaf(x1, wa.x, wa.y)),
                                            lrelu(fmaf(x1, wa.z, wa.w)));
                const unsigned a2 = pack_h2(lrelu(fmaf(x0, wb.x, wb.y)),
                                            lrelu(fmaf(x0, wb.z, wb.w)));
                const unsigned a3 = pack_h2(lrelu(fmaf(x1, wb.x, wb.y)),
                                            lrelu(fmaf(x1, wb.z, wb.w)));

                const uint2* bp = bbase + kt * 256;
                #pragma unroll
                for (int nt = 0; nt < 8; nt++) {
                    const uint2 bf = bp[nt * 32];
                    mma_f16(acc[nt], a0, a1, a2, a3, bf.x, bf.y);
                }
            }

            // ---- epilogue: bias + LeakyReLU, dot w3, reduce, ELU, sum ----
            float s0 = 0.0f, s1 = 0.0f;   // row sums for p0, p1
            #pragma unroll
            for (int nt = 0; nt < 8; nt++) {
                const int j0 = 8 * nt + 2 * tig;
                const float2 e0 = w3b2[d][j0];
                const float2 e1 = w3b2[d][j0 + 1];
                float h;
                h = lrelu(acc[nt][0] + e0.y); s0 = fmaf(h, e0.x, s0);
                h = lrelu(acc[nt][1] + e1.y); s0 = fmaf(h, e1.x, s0);
                h = lrelu(acc[nt][2] + e0.y); s1 = fmaf(h, e0.x, s1);
                h = lrelu(acc[nt][3] + e1.y); s1 = fmaf(h, e1.x, s1);
            }
            // fold tig quad -> full n-sum per point
            s0 += __shfl_xor_sync(0xffffffffu, s0, 1);
            s0 += __shfl_xor_sync(0xffffffffu, s0, 2);
            s1 += __shfl_xor_sync(0xffffffffu, s1, 1);
            s1 += __shfl_xor_sync(0xffffffffu, s1, 2);

            float contrib = 0.0f;
            if (tig == 0) {
                const float b3v = b3s[d];
                float e = s0 + b3v;
                contrib  = (e > 0.f) ? e : expm1f(e);
                e = s1 + b3v;
                contrib += (e > 0.f) ? e : expm1f(e);
                contrib += 2.0f;
            }
            // warp-sum its 16 points
            contrib += __shfl_xor_sync(0xffffffffu, contrib, 4);
            contrib += __shfl_xor_sync(0xffffffffu, contrib, 8);
            contrib += __shfl_xor_sync(0xffffffffu, contrib, 16);

            if (lane == 0) sred[warp][0] = contrib;
            __syncthreads();
            if (tid == 0) {
                float t = 0.0f;
                #pragma unroll
                for (int w = 0; w < 8; w++) t += sred[w][0];
                hz = fmaf(t, dsz, hz);
            }
            __syncthreads();
        }
        if (tid == 0) out[b] = hz;
    }
    (void)red4;
}

extern "C" void kernel_launch(void* const* d_in, const int* in_sizes, int n_in,
                              void* d_out, int out_size)
{
    const float* z   = (const float*)d_in[0];
    const float* u   = (const float*)d_in[1];
    const float* w01 = (const float*)d_in[2];
    const float* b01 = (const float*)d_in[3];
    const float* w02 = (const float*)d_in[4];
    const float* b02 = (const float*)d_in[5];
    const float* w03 = (const float*)d_in[6];
    const float* b03 = (const float*)d_in[7];
    const float* w11 = (const float*)d_in[8];
    const float* b11 = (const float*)d_in[9];
    const float* w12 = (const float*)d_in[10];
    const float* b12 = (const float*)d_in[11];
    const float* w13 = (const float*)d_in[12];
    const float* b13 = (const float*)d_in[13];
    const float* bias= (const float*)d_in[14];
    float* out = (float*)d_out;

    const int B = in_sizes[0] / 2;
    const int grid = (B + BPB - 1) / BPB;
    mono_mlp_fp16_kernel<<<grid, 256>>>(
        z, u, w01, b01, w02, b02, w03, b03,
        w11, b11, w12, b12, w13, b13, bias, out, B);
}

// round 7
// speedup vs baseline: 1.8894x; 1.0064x over previous
#include <cuda_runtime.h>
#include <cuda_fp16.h>
#include <math.h>

#define HID   64
#define NPT   128
#define LBF   (-5.0f)
#define BPB   8      // batches per block

__device__ __forceinline__ unsigned pack_h2(float lo, float hi) {
    const __half2 h = __floats2half2_rn(lo, hi);
    return *reinterpret_cast<const unsigned*>(&h);
}

__device__ __forceinline__ void mma_f16(float c[4],
                                        unsigned a0, unsigned a1, unsigned a2, unsigned a3,
                                        unsigned b0, unsigned b1) {
    asm volatile(
        "mma.sync.aligned.m16n8k16.row.col.f32.f16.f16.f32 "
        "{%0,%1,%2,%3}, {%4,%5,%6,%7}, {%8,%9}, {%0,%1,%2,%3};\n"
        : "+f"(c[0]), "+f"(c[1]), "+f"(c[2]), "+f"(c[3])
        : "r"(a0), "r"(a1), "r"(a2), "r"(a3), "r"(b0), "r"(b1));
}

__device__ __forceinline__ float lrelu(float h) { return fmaxf(h, 0.01f * h); }

__global__ __launch_bounds__(128, 6)
void mono_mlp_fp16r_kernel(const float* __restrict__ z,  const float* __restrict__ u,
                           const float* __restrict__ w01, const float* __restrict__ b01,
                           const float* __restrict__ w02, const float* __restrict__ b02,
                           const float* __restrict__ w03, const float* __restrict__ b03,
                           const float* __restrict__ w11, const float* __restrict__ b11,
                           const float* __restrict__ w12, const float* __restrict__ b12,
                           const float* __restrict__ w13, const float* __restrict__ b13,
                           const float* __restrict__ bias, float* __restrict__ out, int B)
{
    // B fragments (fp16, m16n8k16 order): bfrag[d*1024 + kt*256 + nt*32 + lane]
    //   .x = half2(W2[n][k0], W2[n][k0+1]), .y = half2(W2[n][k0+8], W2[n][k0+9])
    //   n = 8nt + gid, k0 = 16kt + 2tig
    __shared__ uint2  bfrag[2 * 4 * 8 * 32];   // 16 KB (staging; regs hold hot copies)
    __shared__ float4 w1b1p[2][HID / 2];       // (w1[2m], b1[2m], w1[2m+1], b1[2m+1])
    __shared__ float2 w3b2[2][HID];            // (w3[j], b2[j])
    __shared__ float  b3s[2];
    __shared__ float  xs[NPT];                 // layer-0 inputs for current (b,d)
    __shared__ float  sred[2][NPT];            // per-point partials, 2 n-halves
    __shared__ float  red4[4];
    __shared__ float  hzacc[BPB];

    const int tid = threadIdx.x;

    // ---- Prepack weights (once per block) ----
    for (int e = tid; e < 2 * 4 * 8 * 32; e += 128) {
        const int lane = e & 31;
        const int nt   = (e >> 5) & 7;
        const int kt   = (e >> 8) & 3;
        const int d    = (e >> 10) & 1;
        const int n    = 8 * nt + (lane >> 2);
        const int k0   = 16 * kt + 2 * (lane & 3);
        const float* w2 = d ? w12 : w02;
        bfrag[e] = make_uint2(pack_h2(w2[n * 64 + k0],     w2[n * 64 + k0 + 1]),
                              pack_h2(w2[n * 64 + k0 + 8], w2[n * 64 + k0 + 9]));
    }
    for (int i = tid; i < HID / 2; i += 128) {
        w1b1p[0][i] = make_float4(w01[2 * i], b01[2 * i], w01[2 * i + 1], b01[2 * i + 1]);
        w1b1p[1][i] = make_float4(w11[2 * i], b11[2 * i], w11[2 * i + 1], b11[2 * i + 1]);
    }
    for (int i = tid; i < HID; i += 128) {
        w3b2[0][i] = make_float2(w03[i], b02[i]);
        w3b2[1][i] = make_float2(w13[i], b12[i]);
    }
    if (tid == 0) { b3s[0] = b03[0]; b3s[1] = b13[0]; }
    if (tid < BPB) hzacc[tid] = bias[0];
    __syncthreads();

    const int warp  = tid >> 5;
    const int lane  = tid & 31;
    const int gid   = lane >> 2;       // row within m16 group
    const int tig   = lane & 3;        // k / col selector
    const int nhalf = warp & 1;        // n-cols [32*nhalf, +32)
    const int pgrp  = warp >> 1;       // points [64*pgrp, +64)
    const int pbase = 64 * pgrp;
    const int nbase = 32 * nhalf;

    #pragma unroll 1
    for (int d = 0; d < 2; d++) {
        // ---- hoist this warp's 16 B-fragments into persistent registers ----
        uint2 bfr[4][4];
        {
            const uint2* bp = &bfrag[d * 1024 + (4 * nhalf) * 32 + lane];
            #pragma unroll
            for (int kt = 0; kt < 4; kt++)
                #pragma unroll
                for (int ntl = 0; ntl < 4; ntl++)
                    bfr[kt][ntl] = bp[kt * 256 + ntl * 32];
        }
        const float b3v = b3s[d];

        #pragma unroll 1
        for (int bi = 0; bi < BPB; bi++) {
            const int b = blockIdx.x * BPB + bi;

            const float zc  = fmaxf(z[b * 2 + d], LBF);
            const float dsz = (zc - LBF) * (1.0f / (float)(NPT - 1));
            const int   ub  = (b * 2 + d) * (NPT - 1);

            // ---- stage 1: layer-0 inputs for all 128 points (coalesced) ----
            {
                const float uv = (tid < NPT - 1) ? u[ub + tid] : 0.0f;
                xs[tid] = fmaf(dsz, (float)tid + uv, LBF);
            }
            __syncthreads();   // (A)

            // ---- stage 2: GEMM, 4 rounds of 16 points x 32 n-cols ----
            #pragma unroll
            for (int rnd = 0; rnd < 4; rnd++) {
                const int pr = pbase + 16 * rnd;
                const int p0 = pr + gid;       // rows of this lane
                const int p1 = p0 + 8;
                const float x0 = xs[p0];
                const float x1 = xs[p1];

                float acc[4][4];
                #pragma unroll
                for (int ntl = 0; ntl < 4; ntl++)
                    #pragma unroll
                    for (int q = 0; q < 4; q++) acc[ntl][q] = 0.0f;

                #pragma unroll
                for (int kt = 0; kt < 4; kt++) {
                    const float4 wa = w1b1p[d][8 * kt + tig];       // k0, k0+1
                    const float4 wb = w1b1p[d][8 * kt + tig + 4];   // k0+8, k0+9

                    const unsigned a0 = pack_h2(lrelu(fmaf(x0, wa.x, wa.y)),
                                                lrelu(fmaf(x0, wa.z, wa.w)));
                    const unsigned a1 = pack_h2(lrelu(fmaf(x1, wa.x, wa.y)),
                                                lrelu(fmaf(x1, wa.z, wa.w)));
                    const unsigned a2 = pack_h2(lrelu(fmaf(x0, wb.x, wb.y)),
                                                lrelu(fmaf(x0, wb.z, wb.w)));
                    const unsigned a3 = pack_h2(lrelu(fmaf(x1, wb.x, wb.y)),
                                                lrelu(fmaf(x1, wb.z, wb.w)));

                    mma_f16(acc[0][0] ? acc[0] : acc[0], a0, a1, a2, a3,
                            bfr[kt][0].x, bfr[kt][0].y);
                    mma_f16(acc[1], a0, a1, a2, a3, bfr[kt][1].x, bfr[kt][1].y);
                    mma_f16(acc[2], a0, a1, a2, a3, bfr[kt][2].x, bfr[kt][2].y);
                    mma_f16(acc[3], a0, a1, a2, a3, bfr[kt][3].x, bfr[kt][3].y);
                }

                // ---- epilogue for this round ----
                float s0 = 0.0f, s1 = 0.0f;
                #pragma unroll
                for (int ntl = 0; ntl < 4; ntl++) {
                    const int j0 = nbase + 8 * ntl + 2 * tig;
                    const float2 e0 = w3b2[d][j0];
                    const float2 e1 = w3b2[d][j0 + 1];
                    float h;
                    h = lrelu(acc[ntl][0] + e0.y); s0 = fmaf(h, e0.x, s0);
                    h = lrelu(acc[ntl][1] + e1.y); s0 = fmaf(h, e1.x, s0);
                    h = lrelu(acc[ntl][2] + e0.y); s1 = fmaf(h, e0.x, s1);
                    h = lrelu(acc[ntl][3] + e1.y); s1 = fmaf(h, e1.x, s1);
                }
                s0 += __shfl_xor_sync(0xffffffffu, s0, 1);
                s0 += __shfl_xor_sync(0xffffffffu, s0, 2);
                s1 += __shfl_xor_sync(0xffffffffu, s1, 1);
                s1 += __shfl_xor_sync(0xffffffffu, s1, 2);
                if (tig == 0) {
                    sred[nhalf][p0] = s0;
                    sred[nhalf][p1] = s1;
                }
            }
            __syncthreads();   // (B)

            // ---- stage 3: combine n-halves, ELU, block-reduce 128 points ----
            {
                const float v = sred[0][tid] + sred[1][tid] + b3v;
                float t = ((v > 0.f) ? v : expm1f(v)) + 1.0f;
                t += __shfl_xor_sync(0xffffffffu, t, 16);
                t += __shfl_xor_sync(0xffffffffu, t, 8);
                t += __shfl_xor_sync(0xffffffffu, t, 4);
                t += __shfl_xor_sync(0xffffffffu, t, 2);
                t += __shfl_xor_sync(0xffffffffu, t, 1);
                if (lane == 0) red4[warp] = t;
            }
            __syncthreads();   // (C)
            if (tid == 0)
                hzacc[bi] = fmaf(red4[0] + red4[1] + red4[2] + red4[3], dsz, hzacc[bi]);
            __syncthreads();   // (D) red4/sred safe for reuse
        }
    }

    if (tid < BPB) {
        const int b = blockIdx.x * BPB + tid;
        if (b < B) out[b] = hzacc[tid];
    }
}

extern "C" void kernel_launch(void* const* d_in, const int* in_sizes, int n_in,
                              void* d_out, int out_size)
{
    const float* z   = (const float*)d_in[0];
    const float* u   = (const float*)d_in[1];
    const float* w01 = (const float*)d_in[2];
    const float* b01 = (const float*)d_in[3];
    const float* w02 = (const float*)d_in[4];
    const float* b02 = (const float*)d_in[5];
    const float* w03 = (const float*)d_in[6];
    const float* b03 = (const float*)d_in[7];
    const float* w11 = (const float*)d_in[8];
    const float* b11 = (const float*)d_in[9];
    const float* w12 = (const float*)d_in[10];
    const float* b12 = (const float*)d_in[11];
    const float* w13 = (const float*)d_in[12];
    const float* b13 = (const float*)d_in[13];
    const float* bias= (const float*)d_in[14];
    float* out = (float*)d_out;

    const int B = in_sizes[0] / 2;
    const int grid = (B + BPB - 1) / BPB;
    mono_mlp_fp16r_kernel<<<grid, 128>>>(
        z, u, w01, b01, w02, b02, w03, b03,
        w11, b11, w12, b12, w13, b13, bias, out, B);
}

// round 8
// speedup vs baseline: 2.3772x; 1.2582x over previous
#include <cuda_runtime.h>
#include <cuda_fp16.h>
#include <math.h>

#define HID   64
#define NPT   128
#define LBF   (-5.0f)
#define BPB   8      // batches per block

__device__ __forceinline__ unsigned pack_h2(float lo, float hi) {
    const __half2 h = __floats2half2_rn(lo, hi);
    return *reinterpret_cast<const unsigned*>(&h);
}

__device__ __forceinline__ void mma_f16(float c[4],
                                        unsigned a0, unsigned a1, unsigned a2, unsigned a3,
                                        unsigned b0, unsigned b1) {
    asm volatile(
        "mma.sync.aligned.m16n8k16.row.col.f32.f16.f16.f32 "
        "{%0,%1,%2,%3}, {%4,%5,%6,%7}, {%8,%9}, {%0,%1,%2,%3};\n"
        : "+f"(c[0]), "+f"(c[1]), "+f"(c[2]), "+f"(c[3])
        : "r"(a0), "r"(a1), "r"(a2), "r"(a3), "r"(b0), "r"(b1));
}

__device__ __forceinline__ float lrelu(float h) { return fmaxf(h, 0.01f * h); }

// half2 LeakyReLU(0.01): max(h, 0.01*h) elementwise
__device__ __forceinline__ __half2 lrelu2(__half2 h, __half2 c001) {
    return __hmax2(h, __hmul2(h, c001));
}

__global__ __launch_bounds__(128, 7)
void mono_mlp_h2_kernel(const float* __restrict__ z,  const float* __restrict__ u,
                        const float* __restrict__ w01, const float* __restrict__ b01,
                        const float* __restrict__ w02, const float* __restrict__ b02,
                        const float* __restrict__ w03, const float* __restrict__ b03,
                        const float* __restrict__ w11, const float* __restrict__ b11,
                        const float* __restrict__ w12, const float* __restrict__ b12,
                        const float* __restrict__ w13, const float* __restrict__ b13,
                        const float* __restrict__ bias, float* __restrict__ out, int B)
{
    // B fragments (fp16, m16n8k16 order): bfrag[d*1024 + kt*256 + nt*32 + lane]
    __shared__ uint2  bfrag[2 * 4 * 8 * 32];   // 16 KB (staging for reg hoist)
    // layer-1 packed: w1b1h[d][4*kt + tig] = { w1h2(k0,k0+1), b1h2(k0,k0+1),
    //                                          w1h2(k0+8,k0+9), b1h2(k0+8,k0+9) },
    // k0 = 16*kt + 2*tig
    __shared__ uint4  w1b1h[2][16];
    __shared__ float2 w3b2[2][HID];            // (w3[j], b2[j])
    __shared__ float  b3s[2];
    __shared__ float  xs2[BPB][NPT];           // layer-0 inputs, all batches of one d
    __shared__ float  dszs[BPB];
    __shared__ float  sred[2][NPT];            // per-point partials, 2 n-halves
    __shared__ float  red4[4];
    __shared__ float  hzacc[BPB];

    const int tid = threadIdx.x;

    // ---- Prepack weights (once per block) ----
    for (int e = tid; e < 2 * 4 * 8 * 32; e += 128) {
        const int lane = e & 31;
        const int nt   = (e >> 5) & 7;
        const int kt   = (e >> 8) & 3;
        const int d    = (e >> 10) & 1;
        const int n    = 8 * nt + (lane >> 2);
        const int k0   = 16 * kt + 2 * (lane & 3);
        const float* w2 = d ? w12 : w02;
        bfrag[e] = make_uint2(pack_h2(w2[n * 64 + k0],     w2[n * 64 + k0 + 1]),
                              pack_h2(w2[n * 64 + k0 + 8], w2[n * 64 + k0 + 9]));
    }
    if (tid < 32) {
        const int d  = tid >> 4;
        const int j  = tid & 15;           // 4*kt + tig
        const int k0 = 16 * (j >> 2) + 2 * (j & 3);
        const float* w1 = d ? w11 : w01;
        const float* bb = d ? b11 : b01;
        w1b1h[d][j] = make_uint4(pack_h2(w1[k0],     w1[k0 + 1]),
                                 pack_h2(bb[k0],     bb[k0 + 1]),
                                 pack_h2(w1[k0 + 8], w1[k0 + 9]),
                                 pack_h2(bb[k0 + 8], bb[k0 + 9]));
    }
    for (int i = tid; i < HID; i += 128) {
        w3b2[0][i] = make_float2(w03[i], b02[i]);
        w3b2[1][i] = make_float2(w13[i], b12[i]);
    }
    if (tid == 0) { b3s[0] = b03[0]; b3s[1] = b13[0]; }
    if (tid < BPB) hzacc[tid] = bias[0];
    __syncthreads();

    const int warp  = tid >> 5;
    const int lane  = tid & 31;
    const int gid   = lane >> 2;       // row within m16 group
    const int tig   = lane & 3;        // k / col selector
    const int nhalf = warp & 1;        // n-cols [32*nhalf, +32)
    const int pgrp  = warp >> 1;       // points [64*pgrp, +64)
    const int pbase = 64 * pgrp;
    const int nbase = 32 * nhalf;
    const int b0    = blockIdx.x * BPB;
    const __half2 c001 = __float2half2_rn(0.01f);

    #pragma unroll 1
    for (int d = 0; d < 2; d++) {
        // ---- hoist this warp's 16 B-fragments into persistent registers ----
        uint2 bfr[4][4];
        {
            const uint2* bp = &bfrag[d * 1024 + (4 * nhalf) * 32 + lane];
            #pragma unroll
            for (int kt = 0; kt < 4; kt++)
                #pragma unroll
                for (int ntl = 0; ntl < 4; ntl++)
                    bfr[kt][ntl] = bp[kt * 256 + ntl * 32];
        }
        const float b3v = b3s[d];

        // ---- stage 0: layer-0 inputs for all 8 batches of this d ----
        #pragma unroll 1
        for (int it = 0; it < BPB; it++) {
            const int bb_ = b0 + it;
            const float zc  = fmaxf(z[bb_ * 2 + d], LBF);
            const float dsz = (zc - LBF) * (1.0f / (float)(NPT - 1));
            const float uv  = (tid < NPT - 1) ? u[(bb_ * 2 + d) * (NPT - 1) + tid] : 0.0f;
            xs2[it][tid] = fmaf(dsz, (float)tid + uv, LBF);
            if (tid == 0) dszs[it] = dsz;
        }
        __syncthreads();

        #pragma unroll 1
        for (int bi = 0; bi < BPB; bi++) {
            // ---- stage 2: GEMM, 4 rounds of 16 points x 32 n-cols ----
            #pragma unroll
            for (int rnd = 0; rnd < 4; rnd++) {
                const int pr = pbase + 16 * rnd;
                const int p0 = pr + gid;
                const int p1 = p0 + 8;
                const __half2 x0h = __float2half2_rn(xs2[bi][p0]);
                const __half2 x1h = __float2half2_rn(xs2[bi][p1]);

                float acc[4][4];
                #pragma unroll
                for (int ntl = 0; ntl < 4; ntl++)
                    #pragma unroll
                    for (int q = 0; q < 4; q++) acc[ntl][q] = 0.0f;

                #pragma unroll
                for (int kt = 0; kt < 4; kt++) {
                    const uint4 wp = w1b1h[d][4 * kt + tig];
                    const __half2 wlo = *reinterpret_cast<const __half2*>(&wp.x);
                    const __half2 blo = *reinterpret_cast<const __half2*>(&wp.y);
                    const __half2 whi = *reinterpret_cast<const __half2*>(&wp.z);
                    const __half2 bhi = *reinterpret_cast<const __half2*>(&wp.w);

                    const __half2 h0lo = lrelu2(__hfma2(x0h, wlo, blo), c001);
                    const __half2 h1lo = lrelu2(__hfma2(x1h, wlo, blo), c001);
                    const __half2 h0hi = lrelu2(__hfma2(x0h, whi, bhi), c001);
                    const __half2 h1hi = lrelu2(__hfma2(x1h, whi, bhi), c001);
                    const unsigned a0 = *reinterpret_cast<const unsigned*>(&h0lo);
                    const unsigned a1 = *reinterpret_cast<const unsigned*>(&h1lo);
                    const unsigned a2 = *reinterpret_cast<const unsigned*>(&h0hi);
                    const unsigned a3 = *reinterpret_cast<const unsigned*>(&h1hi);

                    mma_f16(acc[0], a0, a1, a2, a3, bfr[kt][0].x, bfr[kt][0].y);
                    mma_f16(acc[1], a0, a1, a2, a3, bfr[kt][1].x, bfr[kt][1].y);
                    mma_f16(acc[2], a0, a1, a2, a3, bfr[kt][2].x, bfr[kt][2].y);
                    mma_f16(acc[3], a0, a1, a2, a3, bfr[kt][3].x, bfr[kt][3].y);
                }

                // ---- epilogue for this round ----
                float s0 = 0.0f, s1 = 0.0f;
                #pragma unroll
                for (int ntl = 0; ntl < 4; ntl++) {
                    const int j0 = nbase + 8 * ntl + 2 * tig;
                    const float2 e0 = w3b2[d][j0];
                    const float2 e1 = w3b2[d][j0 + 1];
                    float h;
                    h = lrelu(acc[ntl][0] + e0.y); s0 = fmaf(h, e0.x, s0);
                    h = lrelu(acc[ntl][1] + e1.y); s0 = fmaf(h, e1.x, s0);
                    h = lrelu(acc[ntl][2] + e0.y); s1 = fmaf(h, e0.x, s1);
                    h = lrelu(acc[ntl][3] + e1.y); s1 = fmaf(h, e1.x, s1);
                }
                s0 += __shfl_xor_sync(0xffffffffu, s0, 1);
                s0 += __shfl_xor_sync(0xffffffffu, s0, 2);
                s1 += __shfl_xor_sync(0xffffffffu, s1, 1);
                s1 += __shfl_xor_sync(0xffffffffu, s1, 2);
                if (tig == 0) {
                    sred[nhalf][p0] = s0;
                    sred[nhalf][p1] = s1;
                }
            }
            __syncthreads();   // (B) sred complete

            // ---- stage 3: combine n-halves, ELU, block-reduce 128 points ----
            {
                const float v = sred[0][tid] + sred[1][tid] + b3v;
                float t = ((v > 0.f) ? v : expm1f(v)) + 1.0f;
                t += __shfl_xor_sync(0xffffffffu, t, 16);
                t += __shfl_xor_sync(0xffffffffu, t, 8);
                t += __shfl_xor_sync(0xffffffffu, t, 4);
                t += __shfl_xor_sync(0xffffffffu, t, 2);
                t += __shfl_xor_sync(0xffffffffu, t, 1);
                if (lane == 0) red4[warp] = t;
            }
            __syncthreads();   // (C) red4 complete; also orders next sred writes
            if (tid == 0)
                hzacc[bi] = fmaf(red4[0] + red4[1] + red4[2] + red4[3],
                                 dszs[bi], hzacc[bi]);
            // tid0's red4 read completes before it reaches next (B); writers
            // only overwrite red4 after their next (B) -> no extra barrier.
        }
        __syncthreads();   // protect xs2/dszs before next-d refill
    }

    if (tid < BPB) {
        const int b = b0 + tid;
        if (b < B) out[b] = hzacc[tid];
    }
}

extern "C" void kernel_launch(void* const* d_in, const int* in_sizes, int n_in,
                              void* d_out, int out_size)
{
    const float* z   = (const float*)d_in[0];
    const float* u   = (const float*)d_in[1];
    const float* w01 = (const float*)d_in[2];
    const float* b01 = (const float*)d_in[3];
    const float* w02 = (const float*)d_in[4];
    const float* b02 = (const float*)d_in[5];
    const float* w03 = (const float*)d_in[6];
    const float* b03 = (const float*)d_in[7];
    const float* w11 = (const float*)d_in[8];
    const float* b11 = (const float*)d_in[9];
    const float* w12 = (const float*)d_in[10];
    const float* b12 = (const float*)d_in[11];
    const float* w13 = (const float*)d_in[12];
    const float* b13 = (const float*)d_in[13];
    const float* bias= (const float*)d_in[14];
    float* out = (float*)d_out;

    const int B = in_sizes[0] / 2;
    const int grid = (B + BPB - 1) / BPB;
    mono_mlp_h2_kernel<<<grid, 128>>>(
        z, u, w01, b01, w02, b02, w03, b03,
        w11, b11, w12, b12, w13, b13, bias, out, B);
}

// round 9
// speedup vs baseline: 2.5591x; 1.0765x over previous
#include <cuda_runtime.h>
#include <cuda_fp16.h>
#include <math.h>

#define HID   64
#define NPT   128
#define LBF   (-5.0f)
#define BPB   8      // batches per block

__device__ __forceinline__ unsigned pack_h2(float lo, float hi) {
    const __half2 h = __floats2half2_rn(lo, hi);
    return *reinterpret_cast<const unsigned*>(&h);
}

__device__ __forceinline__ void mma_f16(float c[4],
                                        unsigned a0, unsigned a1, unsigned a2, unsigned a3,
                                        unsigned b0, unsigned b1) {
    asm volatile(
        "mma.sync.aligned.m16n8k16.row.col.f32.f16.f16.f32 "
        "{%0,%1,%2,%3}, {%4,%5,%6,%7}, {%8,%9}, {%0,%1,%2,%3};\n"
        : "+f"(c[0]), "+f"(c[1]), "+f"(c[2]), "+f"(c[3])
        : "r"(a0), "r"(a1), "r"(a2), "r"(a3), "r"(b0), "r"(b1));
}

// half2 LeakyReLU(0.01): max(h, 0.01*h) elementwise
__device__ __forceinline__ __half2 lrelu2(__half2 h, __half2 c001) {
    return __hmax2(h, __hmul2(h, c001));
}

__global__ __launch_bounds__(128, 7)
void mono_mlp_h2e_kernel(const float* __restrict__ z,  const float* __restrict__ u,
                         const float* __restrict__ w01, const float* __restrict__ b01,
                         const float* __restrict__ w02, const float* __restrict__ b02,
                         const float* __restrict__ w03, const float* __restrict__ b03,
                         const float* __restrict__ w11, const float* __restrict__ b11,
                         const float* __restrict__ w12, const float* __restrict__ b12,
                         const float* __restrict__ w13, const float* __restrict__ b13,
                         const float* __restrict__ bias, float* __restrict__ out, int B)
{
    // B fragments (fp16, m16n8k16 order): bfrag[d*1024 + kt*256 + nt*32 + lane]
    __shared__ uint2  bfrag[2 * 4 * 8 * 32];   // 16 KB (staging for reg hoist)
    // layer-1 packed: w1b1h[d][4*kt + tig] = { w1h2(k0,k0+1), b1h2(k0,k0+1),
    //                                          w1h2(k0+8,k0+9), b1h2(k0+8,k0+9) }
    __shared__ uint4  w1b1h[2][16];
    // epilogue packed: w3b2h[d][jp] = { h2(w3[2jp], w3[2jp+1]), h2(b2[2jp], b2[2jp+1]) }
    __shared__ uint2  w3b2h[2][32];
    __shared__ float  b3s[2];
    __shared__ unsigned xs2h[BPB][NPT];        // x broadcast as half2, all batches of one d
    __shared__ float  dszs[BPB];
    __shared__ float  sred[2][NPT];            // per-point partials, 2 n-halves
    __shared__ float  red4[4];
    __shared__ float  hzacc[BPB];

    const int tid = threadIdx.x;

    // ---- Prepack weights (once per block) ----
    for (int e = tid; e < 2 * 4 * 8 * 32; e += 128) {
        const int lane = e & 31;
        const int nt   = (e >> 5) & 7;
        const int kt   = (e >> 8) & 3;
        const int d    = (e >> 10) & 1;
        const int n    = 8 * nt + (lane >> 2);
        const int k0   = 16 * kt + 2 * (lane & 3);
        const float* w2 = d ? w12 : w02;
        bfrag[e] = make_uint2(pack_h2(w2[n * 64 + k0],     w2[n * 64 + k0 + 1]),
                              pack_h2(w2[n * 64 + k0 + 8], w2[n * 64 + k0 + 9]));
    }
    if (tid < 32) {
        const int d  = tid >> 4;
        const int j  = tid & 15;           // 4*kt + tig
        const int k0 = 16 * (j >> 2) + 2 * (j & 3);
        const float* w1 = d ? w11 : w01;
        const float* bb = d ? b11 : b01;
        w1b1h[d][j] = make_uint4(pack_h2(w1[k0],     w1[k0 + 1]),
                                 pack_h2(bb[k0],     bb[k0 + 1]),
                                 pack_h2(w1[k0 + 8], w1[k0 + 9]),
                                 pack_h2(bb[k0 + 8], bb[k0 + 9]));
    }
    if (tid < 64) {
        const int d  = tid >> 5;
        const int jp = tid & 31;
        const int j  = 2 * jp;
        const float* w3 = d ? w13 : w03;
        const float* b2 = d ? b12 : b02;
        w3b2h[d][jp] = make_uint2(pack_h2(w3[j], w3[j + 1]),
                                  pack_h2(b2[j], b2[j + 1]));
    }
    if (tid == 0) { b3s[0] = b03[0]; b3s[1] = b13[0]; }
    if (tid < BPB) hzacc[tid] = bias[0];
    __syncthreads();

    const int warp  = tid >> 5;
    const int lane  = tid & 31;
    const int gid   = lane >> 2;       // row within m16 group
    const int tig   = lane & 3;        // k / col selector
    const int nhalf = warp & 1;        // n-cols [32*nhalf, +32)
    const int pgrp  = warp >> 1;       // points [64*pgrp, +64)
    const int pbase = 64 * pgrp;
    const int b0    = blockIdx.x * BPB;
    const __half2 c001 = __float2half2_rn(0.01f);
    const __half2 hzero = __float2half2_rn(0.0f);

    #pragma unroll 1
    for (int d = 0; d < 2; d++) {
        // ---- hoist this warp's 16 B-fragments into persistent registers ----
        uint2 bfr[4][4];
        {
            const uint2* bp = &bfrag[d * 1024 + (4 * nhalf) * 32 + lane];
            #pragma unroll
            for (int kt = 0; kt < 4; kt++)
                #pragma unroll
                for (int ntl = 0; ntl < 4; ntl++)
                    bfr[kt][ntl] = bp[kt * 256 + ntl * 32];
        }
        const float b3v = b3s[d];

        // ---- stage 0: layer-0 inputs for all 8 batches of this d ----
        #pragma unroll 1
        for (int it = 0; it < BPB; it++) {
            const int bb_ = b0 + it;
            const float zc  = fmaxf(z[bb_ * 2 + d], LBF);
            const float dsz = (zc - LBF) * (1.0f / (float)(NPT - 1));
            const float uv  = (tid < NPT - 1) ? u[(bb_ * 2 + d) * (NPT - 1) + tid] : 0.0f;
            const float x   = fmaf(dsz, (float)tid + uv, LBF);
            xs2h[it][tid] = pack_h2(x, x);
            if (tid == 0) dszs[it] = dsz;
        }
        __syncthreads();

        #pragma unroll 1
        for (int bi = 0; bi < BPB; bi++) {
            // ---- stage 2: GEMM, 4 rounds of 16 points x 32 n-cols ----
            #pragma unroll
            for (int rnd = 0; rnd < 4; rnd++) {
                const int pr = pbase + 16 * rnd;
                const int p0 = pr + gid;
                const int p1 = p0 + 8;
                const __half2 x0h = *reinterpret_cast<const __half2*>(&xs2h[bi][p0]);
                const __half2 x1h = *reinterpret_cast<const __half2*>(&xs2h[bi][p1]);

                float acc[4][4];
                #pragma unroll
                for (int ntl = 0; ntl < 4; ntl++)
                    #pragma unroll
                    for (int q = 0; q < 4; q++) acc[ntl][q] = 0.0f;

                #pragma unroll
                for (int kt = 0; kt < 4; kt++) {
                    const uint4 wp = w1b1h[d][4 * kt + tig];
                    const __half2 wlo = *reinterpret_cast<const __half2*>(&wp.x);
                    const __half2 blo = *reinterpret_cast<const __half2*>(&wp.y);
                    const __half2 whi = *reinterpret_cast<const __half2*>(&wp.z);
                    const __half2 bhi = *reinterpret_cast<const __half2*>(&wp.w);

                    const __half2 h0lo = lrelu2(__hfma2(x0h, wlo, blo), c001);
                    const __half2 h1lo = lrelu2(__hfma2(x1h, wlo, blo), c001);
                    const __half2 h0hi = lrelu2(__hfma2(x0h, whi, bhi), c001);
                    const __half2 h1hi = lrelu2(__hfma2(x1h, whi, bhi), c001);
                    const unsigned a0 = *reinterpret_cast<const unsigned*>(&h0lo);
                    const unsigned a1 = *reinterpret_cast<const unsigned*>(&h1lo);
                    const unsigned a2 = *reinterpret_cast<const unsigned*>(&h0hi);
                    const unsigned a3 = *reinterpret_cast<const unsigned*>(&h1hi);

                    mma_f16(acc[0], a0, a1, a2, a3, bfr[kt][0].x, bfr[kt][0].y);
                    mma_f16(acc[1], a0, a1, a2, a3, bfr[kt][1].x, bfr[kt][1].y);
                    mma_f16(acc[2], a0, a1, a2, a3, bfr[kt][2].x, bfr[kt][2].y);
                    mma_f16(acc[3], a0, a1, a2, a3, bfr[kt][3].x, bfr[kt][3].y);
                }

                // ---- epilogue for this round (half2) ----
                __half2 s0h = hzero, s1h = hzero;
                #pragma unroll
                for (int ntl = 0; ntl < 4; ntl++) {
                    const uint2 wb = w3b2h[d][16 * nhalf + 4 * ntl + tig];
                    const __half2 w3p = *reinterpret_cast<const __half2*>(&wb.x);
                    const __half2 b2p = *reinterpret_cast<const __half2*>(&wb.y);
                    const __half2 p0p = __floats2half2_rn(acc[ntl][0], acc[ntl][1]);
                    const __half2 p1p = __floats2half2_rn(acc[ntl][2], acc[ntl][3]);
                    s0h = __hfma2(lrelu2(__hadd2(p0p, b2p), c001), w3p, s0h);
                    s1h = __hfma2(lrelu2(__hadd2(p1p, b2p), c001), w3p, s1h);
                }
                float s0 = __low2float(s0h) + __high2float(s0h);
                float s1 = __low2float(s1h) + __high2float(s1h);
                s0 += __shfl_xor_sync(0xffffffffu, s0, 1);
                s0 += __shfl_xor_sync(0xffffffffu, s0, 2);
                s1 += __shfl_xor_sync(0xffffffffu, s1, 1);
                s1 += __shfl_xor_sync(0xffffffffu, s1, 2);
                if (tig == 0) {
                    sred[nhalf][p0] = s0;
                    sred[nhalf][p1] = s1;
                }
            }
            __syncthreads();   // (B) sred complete

            // ---- stage 3: combine n-halves, ELU, block-reduce 128 points ----
            {
                const float v = sred[0][tid] + sred[1][tid] + b3v;
                float t = ((v > 0.f) ? v : expm1f(v)) + 1.0f;
                t += __shfl_xor_sync(0xffffffffu, t, 16);
                t += __shfl_xor_sync(0xffffffffu, t, 8);
                t += __shfl_xor_sync(0xffffffffu, t, 4);
                t += __shfl_xor_sync(0xffffffffu, t, 2);
                t += __shfl_xor_sync(0xffffffffu, t, 1);
                if (lane == 0) red4[warp] = t;
            }
            __syncthreads();   // (C) red4 complete; also orders next sred writes
            if (tid == 0)
                hzacc[bi] = fmaf(red4[0] + red4[1] + red4[2] + red4[3],
                                 dszs[bi], hzacc[bi]);
        }
        __syncthreads();   // protect xs2h/dszs before next-d refill
    }

    if (tid < BPB) {
        const int b = b0 + tid;
        if (b < B) out[b] = hzacc[tid];
    }
}

extern "C" void kernel_launch(void* const* d_in, const int* in_sizes, int n_in,
                              void* d_out, int out_size)
{
    const float* z   = (const float*)d_in[0];
    const float* u   = (const float*)d_in[1];
    const float* w01 = (const float*)d_in[2];
    const float* b01 = (const float*)d_in[3];
    const float* w02 = (const float*)d_in[4];
    const float* b02 = (const float*)d_in[5];
    const float* w03 = (const float*)d_in[6];
    const float* b03 = (const float*)d_in[7];
    const float* w11 = (const float*)d_in[8];
    const float* b11 = (const float*)d_in[9];
    const float* w12 = (const float*)d_in[10];
    const float* b12 = (const float*)d_in[11];
    const float* w13 = (const float*)d_in[12];
    const float* b13 = (const float*)d_in[13];
    const float* bias= (const float*)d_in[14];
    float* out = (float*)d_out;

    const int B = in_sizes[0] / 2;
    const int grid = (B + BPB - 1) / BPB;
    mono_mlp_h2e_kernel<<<grid, 128>>>(
        z, u, w01, b01, w02, b02, w03, b03,
        w11, b11, w12, b12, w13, b13, bias, out, B);
}

// round 10
// speedup vs baseline: 2.6889x; 1.0507x over previous
#include <cuda_runtime.h>
#include <cuda_fp16.h>
#include <math.h>

#define HID   64
#define NPT   128
#define LBF   (-5.0f)
#define BPB   8      // batches per block

__device__ __forceinline__ unsigned pack_h2(float lo, float hi) {
    const __half2 h = __floats2half2_rn(lo, hi);
    return *reinterpret_cast<const unsigned*>(&h);
}

// fp16-accumulator mma: C/D are two f16x2 regs
//   c[0] = half2(C[row=gid][2tig], C[row=gid][2tig+1])
//   c[1] = half2(C[row=gid+8][2tig], C[row=gid+8][2tig+1])
__device__ __forceinline__ void mma_f16acc(unsigned c[2],
                                           unsigned a0, unsigned a1, unsigned a2, unsigned a3,
                                           unsigned b0, unsigned b1) {
    asm volatile(
        "mma.sync.aligned.m16n8k16.row.col.f16.f16.f16.f16 "
        "{%0,%1}, {%2,%3,%4,%5}, {%6,%7}, {%0,%1};\n"
        : "+r"(c[0]), "+r"(c[1])
        : "r"(a0), "r"(a1), "r"(a2), "r"(a3), "r"(b0), "r"(b1));
}

// half2 LeakyReLU(0.01): max(h, 0.01*h) elementwise
__device__ __forceinline__ __half2 lrelu2(__half2 h, __half2 c001) {
    return __hmax2(h, __hmul2(h, c001));
}

__global__ __launch_bounds__(128, 8)
void mono_mlp_h2a_kernel(const float* __restrict__ z,  const float* __restrict__ u,
                         const float* __restrict__ w01, const float* __restrict__ b01,
                         const float* __restrict__ w02, const float* __restrict__ b02,
                         const float* __restrict__ w03, const float* __restrict__ b03,
                         const float* __restrict__ w11, const float* __restrict__ b11,
                         const float* __restrict__ w12, const float* __restrict__ b12,
                         const float* __restrict__ w13, const float* __restrict__ b13,
                         const float* __restrict__ bias, float* __restrict__ out, int B)
{
    // B fragments (fp16, m16n8k16 order): bfrag[d*1024 + kt*256 + nt*32 + lane]
    __shared__ uint2  bfrag[2 * 4 * 8 * 32];   // 16 KB (staging for reg hoist)
    // layer-1 packed: w1b1h[d][4*kt + tig]
    __shared__ uint4  w1b1h[2][16];
    // epilogue packed: w3b2h[d][jp] = { h2(w3[2jp], w3[2jp+1]), h2(b2[2jp], b2[2jp+1]) }
    __shared__ uint2  w3b2h[2][32];
    __shared__ float  b3s[2];
    __shared__ unsigned xs2h[BPB][NPT];        // x broadcast as half2
    __shared__ float  dszs[BPB];
    __shared__ float  sred[2][NPT];            // per-point partials, 2 n-halves
    __shared__ float  red4[4];
    __shared__ float  hzacc[BPB];

    const int tid = threadIdx.x;

    // ---- Prepack weights (once per block) ----
    for (int e = tid; e < 2 * 4 * 8 * 32; e += 128) {
        const int lane = e & 31;
        const int nt   = (e >> 5) & 7;
        const int kt   = (e >> 8) & 3;
        const int d    = (e >> 10) & 1;
        const int n    = 8 * nt + (lane >> 2);
        const int k0   = 16 * kt + 2 * (lane & 3);
        const float* w2 = d ? w12 : w02;
        bfrag[e] = make_uint2(pack_h2(w2[n * 64 + k0],     w2[n * 64 + k0 + 1]),
                              pack_h2(w2[n * 64 + k0 + 8], w2[n * 64 + k0 + 9]));
    }
    if (tid < 32) {
        const int d  = tid >> 4;
        const int j  = tid & 15;           // 4*kt + tig
        const int k0 = 16 * (j >> 2) + 2 * (j & 3);
        const float* w1 = d ? w11 : w01;
        const float* bb = d ? b11 : b01;
        w1b1h[d][j] = make_uint4(pack_h2(w1[k0],     w1[k0 + 1]),
                                 pack_h2(bb[k0],     bb[k0 + 1]),
                                 pack_h2(w1[k0 + 8], w1[k0 + 9]),
                                 pack_h2(bb[k0 + 8], bb[k0 + 9]));
    }
    if (tid < 64) {
        const int d  = tid >> 5;
        const int jp = tid & 31;
        const int j  = 2 * jp;
        const float* w3 = d ? w13 : w03;
        const float* b2 = d ? b12 : b02;
        w3b2h[d][jp] = make_uint2(pack_h2(w3[j], w3[j + 1]),
                                  pack_h2(b2[j], b2[j + 1]));
    }
    if (tid == 0) { b3s[0] = b03[0]; b3s[1] = b13[0]; }
    if (tid < BPB) hzacc[tid] = bias[0];
    __syncthreads();

    const int warp  = tid >> 5;
    const int lane  = tid & 31;
    const int gid   = lane >> 2;       // row within m16 group
    const int tig   = lane & 3;        // k / col selector
    const int nhalf = warp & 1;        // n-cols [32*nhalf, +32)
    const int pgrp  = warp >> 1;       // points [64*pgrp, +64)
    const int pbase = 64 * pgrp;
    const int b0    = blockIdx.x * BPB;
    const __half2 c001 = __float2half2_rn(0.01f);
    const __half2 hzero = __float2half2_rn(0.0f);

    #pragma unroll 1
    for (int d = 0; d < 2; d++) {
        // ---- hoist this warp's 16 B-fragments into persistent registers ----
        uint2 bfr[4][4];
        {
            const uint2* bp = &bfrag[d * 1024 + (4 * nhalf) * 32 + lane];
            #pragma unroll
            for (int kt = 0; kt < 4; kt++)
                #pragma unroll
                for (int ntl = 0; ntl < 4; ntl++)
                    bfr[kt][ntl] = bp[kt * 256 + ntl * 32];
        }
        const float b3v = b3s[d];

        // ---- stage 0: layer-0 inputs for all 8 batches of this d ----
        #pragma unroll 1
        for (int it = 0; it < BPB; it++) {
            const int bb_ = b0 + it;
            const float zc  = fmaxf(z[bb_ * 2 + d], LBF);
            const float dsz = (zc - LBF) * (1.0f / (float)(NPT - 1));
            const float uv  = (tid < NPT - 1) ? u[(bb_ * 2 + d) * (NPT - 1) + tid] : 0.0f;
            const float x   = fmaf(dsz, (float)tid + uv, LBF);
            xs2h[it][tid] = pack_h2(x, x);
            if (tid == 0) dszs[it] = dsz;
        }
        __syncthreads();

        #pragma unroll 1
        for (int bi = 0; bi < BPB; bi++) {
            // ---- stage 2: GEMM, 4 rounds of 16 points x 32 n-cols ----
            #pragma unroll
            for (int rnd = 0; rnd < 4; rnd++) {
                const int pr = pbase + 16 * rnd;
                const int p0 = pr + gid;
                const int p1 = p0 + 8;
                const __half2 x0h = *reinterpret_cast<const __half2*>(&xs2h[bi][p0]);
                const __half2 x1h = *reinterpret_cast<const __half2*>(&xs2h[bi][p1]);

                unsigned acc[4][2];
                #pragma unroll
                for (int ntl = 0; ntl < 4; ntl++) { acc[ntl][0] = 0u; acc[ntl][1] = 0u; }

                #pragma unroll
                for (int kt = 0; kt < 4; kt++) {
                    const uint4 wp = w1b1h[d][4 * kt + tig];
                    const __half2 wlo = *reinterpret_cast<const __half2*>(&wp.x);
                    const __half2 blo = *reinterpret_cast<const __half2*>(&wp.y);
                    const __half2 whi = *reinterpret_cast<const __half2*>(&wp.z);
                    const __half2 bhi = *reinterpret_cast<const __half2*>(&wp.w);

                    const __half2 h0lo = lrelu2(__hfma2(x0h, wlo, blo), c001);
                    const __half2 h1lo = lrelu2(__hfma2(x1h, wlo, blo), c001);
                    const __half2 h0hi = lrelu2(__hfma2(x0h, whi, bhi), c001);
                    const __half2 h1hi = lrelu2(__hfma2(x1h, whi, bhi), c001);
                    const unsigned a0 = *reinterpret_cast<const unsigned*>(&h0lo);
                    const unsigned a1 = *reinterpret_cast<const unsigned*>(&h1lo);
                    const unsigned a2 = *reinterpret_cast<const unsigned*>(&h0hi);
                    const unsigned a3 = *reinterpret_cast<const unsigned*>(&h1hi);

                    mma_f16acc(acc[0], a0, a1, a2, a3, bfr[kt][0].x, bfr[kt][0].y);
                    mma_f16acc(acc[1], a0, a1, a2, a3, bfr[kt][1].x, bfr[kt][1].y);
                    mma_f16acc(acc[2], a0, a1, a2, a3, bfr[kt][2].x, bfr[kt][2].y);
                    mma_f16acc(acc[3], a0, a1, a2, a3, bfr[kt][3].x, bfr[kt][3].y);
                }

                // ---- epilogue (half2, no cvt needed: acc is already packed) ----
                __half2 s0h = hzero, s1h = hzero;
                #pragma unroll
                for (int ntl = 0; ntl < 4; ntl++) {
                    const uint2 wb = w3b2h[d][16 * nhalf + 4 * ntl + tig];
                    const __half2 w3p = *reinterpret_cast<const __half2*>(&wb.x);
                    const __half2 b2p = *reinterpret_cast<const __half2*>(&wb.y);
                    const __half2 p0p = *reinterpret_cast<const __half2*>(&acc[ntl][0]);
                    const __half2 p1p = *reinterpret_cast<const __half2*>(&acc[ntl][1]);
                    s0h = __hfma2(lrelu2(__hadd2(p0p, b2p), c001), w3p, s0h);
                    s1h = __hfma2(lrelu2(__hadd2(p1p, b2p), c001), w3p, s1h);
                }
                float s0 = __low2float(s0h) + __high2float(s0h);
                float s1 = __low2float(s1h) + __high2float(s1h);
                s0 += __shfl_xor_sync(0xffffffffu, s0, 1);
                s0 += __shfl_xor_sync(0xffffffffu, s0, 2);
                s1 += __shfl_xor_sync(0xffffffffu, s1, 1);
                s1 += __shfl_xor_sync(0xffffffffu, s1, 2);
                if (tig == 0) {
                    sred[nhalf][p0] = s0;
                    sred[nhalf][p1] = s1;
                }
            }
            __syncthreads();   // (B) sred complete

            // ---- stage 3: combine n-halves, ELU, block-reduce 128 points ----
            {
                const float v = sred[0][tid] + sred[1][tid] + b3v;
                float t = ((v > 0.f) ? v : expm1f(v)) + 1.0f;
                t += __shfl_xor_sync(0xffffffffu, t, 16);
                t += __shfl_xor_sync(0xffffffffu, t, 8);
                t += __shfl_xor_sync(0xffffffffu, t, 4);
                t += __shfl_xor_sync(0xffffffffu, t, 2);
                t += __shfl_xor_sync(0xffffffffu, t, 1);
                if (lane == 0) red4[warp] = t;
            }
            __syncthreads();   // (C) red4 complete; also orders next sred writes
            if (tid == 0)
                hzacc[bi] = fmaf(red4[0] + red4[1] + red4[2] + red4[3],
                                 dszs[bi], hzacc[bi]);
        }
        __syncthreads();   // protect xs2h/dszs before next-d refill
    }

    if (tid < BPB) {
        const int b = b0 + tid;
        if (b < B) out[b] = hzacc[tid];
    }
}

extern "C" void kernel_launch(void* const* d_in, const int* in_sizes, int n_in,
                              void* d_out, int out_size)
{
    const float* z   = (const float*)d_in[0];
    const float* u   = (const float*)d_in[1];
    const float* w01 = (const float*)d_in[2];
    const float* b01 = (const float*)d_in[3];
    const float* w02 = (const float*)d_in[4];
    const float* b02 = (const float*)d_in[5];
    const float* w03 = (const float*)d_in[6];
    const float* b03 = (const float*)d_in[7];
    const float* w11 = (const float*)d_in[8];
    const float* b11 = (const float*)d_in[9];
    const float* w12 = (const float*)d_in[10];
    const float* b12 = (const float*)d_in[11];
    const float* w13 = (const float*)d_in[12];
    const float* b13 = (const float*)d_in[13];
    const float* bias= (const float*)d_in[14];
    float* out = (float*)d_out;

    const int B = in_sizes[0] / 2;
    const int grid = (B + BPB - 1) / BPB;
    mono_mlp_h2a_kernel<<<grid, 128>>>(
        z, u, w01, b01, w02, b02, w03, b03,
        w11, b11, w12, b12, w13, b13, bias, out, B);
}